// round 7
// baseline (speedup 1.0000x reference)
#include <cuda_runtime.h>
#include <math.h>

#define TT   32     // timesteps
#define BB   128    // traces (collapsed batch)
#define HID  128
#define G4   512    // 4*HID
#define WPAD 68     // smem weight row stride (floats), 16B-aligned, conflict-minimal

// ---------------- scratch (static device globals; no allocation) ----------------
__device__ float g_P [TT * BB * G4];   // x-projection + biases, [t][trace][512]  (8 MB, reused for both layers)
__device__ float g_h1[TT * BB * HID];  // layer-0 hidden stream [t][trace][128]
__device__ float g_h2[TT * BB * HID];  // layer-1 hidden stream

__device__ __forceinline__ float sigf(float x) { return 1.0f / (1.0f + expf(-x)); }

// ---------------- x-projection GEMM ----------------
// C[m][n] = sum_k A[arow(m)][k] * W[n][k] + b1[n] + b2[n]
// m = t*128 + trace ; REMAP: arow = trace*32 + t (layer-0 input layout), else arow = m.
template<int KTOT, bool REMAP>
__global__ void __launch_bounds__(256)
xproj_gemm(const float* __restrict__ Aext,
           const float* __restrict__ W,
           const float* __restrict__ b1,
           const float* __restrict__ b2)
{
    __shared__ float As[64][65];
    __shared__ float Ws[64][65];

    const float* A = REMAP ? Aext : g_h1;   // layer-1 consumes g_h1 directly

    const int m0 = blockIdx.x * 64;
    const int n0 = blockIdx.y * 64;
    const int tx = threadIdx.x;
    const int trow = (tx >> 4) * 4;   // 0..60
    const int tcol = (tx & 15) * 4;   // 0..60

    float acc[4][4];
#pragma unroll
    for (int i = 0; i < 4; i++)
#pragma unroll
        for (int j = 0; j < 4; j++) acc[i][j] = 0.0f;

    for (int kc = 0; kc < KTOT; kc += 64) {
        // load A tile 64x64
#pragma unroll
        for (int it = 0; it < 4; it++) {
            int i  = tx + it * 256;
            int r  = i >> 4;
            int c4 = (i & 15) << 2;
            int m  = m0 + r;
            int arow = REMAP ? ((m & 127) * TT + (m >> 7)) : m;
            float4 v = *(const float4*)(A + arow * KTOT + kc + c4);
            As[r][c4 + 0] = v.x; As[r][c4 + 1] = v.y;
            As[r][c4 + 2] = v.z; As[r][c4 + 3] = v.w;
        }
        // load W tile 64x64
#pragma unroll
        for (int it = 0; it < 4; it++) {
            int i  = tx + it * 256;
            int r  = i >> 4;
            int c4 = (i & 15) << 2;
            float4 v = *(const float4*)(W + (n0 + r) * KTOT + kc + c4);
            Ws[r][c4 + 0] = v.x; Ws[r][c4 + 1] = v.y;
            Ws[r][c4 + 2] = v.z; Ws[r][c4 + 3] = v.w;
        }
        __syncthreads();

#pragma unroll
        for (int k = 0; k < 64; k++) {
            float a0 = As[trow + 0][k], a1 = As[trow + 1][k];
            float a2 = As[trow + 2][k], a3 = As[trow + 3][k];
            float w0 = Ws[tcol + 0][k], w1 = Ws[tcol + 1][k];
            float w2 = Ws[tcol + 2][k], w3 = Ws[tcol + 3][k];
            acc[0][0] += a0 * w0; acc[0][1] += a0 * w1; acc[0][2] += a0 * w2; acc[0][3] += a0 * w3;
            acc[1][0] += a1 * w0; acc[1][1] += a1 * w1; acc[1][2] += a1 * w2; acc[1][3] += a1 * w3;
            acc[2][0] += a2 * w0; acc[2][1] += a2 * w1; acc[2][2] += a2 * w2; acc[2][3] += a2 * w3;
            acc[3][0] += a3 * w0; acc[3][1] += a3 * w1; acc[3][2] += a3 * w2; acc[3][3] += a3 * w3;
        }
        __syncthreads();
    }

    float bias[4];
#pragma unroll
    for (int j = 0; j < 4; j++) {
        int n = n0 + tcol + j;
        bias[j] = b1[n] + b2[n];
    }
#pragma unroll
    for (int i = 0; i < 4; i++) {
        int m = m0 + trow + i;
        float4 o;
        o.x = acc[i][0] + bias[0];
        o.y = acc[i][1] + bias[1];
        o.z = acc[i][2] + bias[2];
        o.w = acc[i][3] + bias[3];
        *(float4*)(g_P + m * G4 + n0 + tcol) = o;
    }
}

// ---------------- recurrent scan: one CTA per trace ----------------
// 512 threads. Thread tid owns gate row tid: W_hh[tid][0:64] in registers,
// W_hh[tid][64:128] in shared. h double-buffered in shared. c lives in
// registers of threads 0..127. Reads g_P, writes g_h1 (layer 0) or g_h2.
__global__ void __launch_bounds__(512, 1)
lstm_scan(const float* __restrict__ W_hh, int layer)
{
    extern __shared__ float sm[];
    float* h_sm = sm;                 // 2 * 128
    float* gate = sm + 2 * HID;       // 512
    float* Wsm  = sm + 2 * HID + G4;  // 512 * WPAD

    const int tid   = threadIdx.x;    // gate row 0..511
    const int trace = blockIdx.x;     // 0..127
    float* __restrict__ h_out = layer ? g_h2 : g_h1;

    // ---- preload weights ----
    float w[64];
    const float4* wrow = (const float4*)(W_hh + tid * HID);
#pragma unroll
    for (int k4 = 0; k4 < 16; k4++) {
        float4 v = wrow[k4];
        w[4 * k4 + 0] = v.x; w[4 * k4 + 1] = v.y;
        w[4 * k4 + 2] = v.z; w[4 * k4 + 3] = v.w;
    }
#pragma unroll
    for (int k4 = 0; k4 < 16; k4++) {
        float4 v = wrow[16 + k4];
        *(float4*)&Wsm[tid * WPAD + 4 * k4] = v;
    }
    if (tid < 2 * HID) h_sm[tid] = 0.0f;
    float c = 0.0f;
    __syncthreads();

    const float* __restrict__ Pb = g_P + trace * G4 + tid;

    for (int t = 0; t < TT; t++) {
        const float* hb = h_sm + (t & 1) * HID;   // h_{t-1}
        float acc0 = Pb[t * BB * G4];             // x-proj + biases
        float acc1 = 0.0f, acc2 = 0.0f, acc3 = 0.0f;

#pragma unroll
        for (int k4 = 0; k4 < 16; k4++) {         // K = 0..63 (register weights)
            float4 hv = *(const float4*)(hb + 4 * k4);
            acc0 += w[4 * k4 + 0] * hv.x;
            acc1 += w[4 * k4 + 1] * hv.y;
            acc2 += w[4 * k4 + 2] * hv.z;
            acc3 += w[4 * k4 + 3] * hv.w;
        }
#pragma unroll
        for (int k4 = 0; k4 < 16; k4++) {         // K = 64..127 (smem weights)
            float4 hv = *(const float4*)(hb + 64 + 4 * k4);
            float4 wv = *(const float4*)&Wsm[tid * WPAD + 4 * k4];
            acc0 += wv.x * hv.x;
            acc1 += wv.y * hv.y;
            acc2 += wv.z * hv.z;
            acc3 += wv.w * hv.w;
        }
        gate[tid] = (acc0 + acc1) + (acc2 + acc3);
        __syncthreads();

        if (tid < HID) {
            float ig = sigf(gate[tid]);
            float fg = sigf(gate[HID + tid]);
            float gg = tanhf(gate[2 * HID + tid]);
            float og = sigf(gate[3 * HID + tid]);
            c = fg * c + ig * gg;
            float h = og * tanhf(c);
            h_sm[((t + 1) & 1) * HID + tid] = h;
            h_out[(t * BB + trace) * HID + tid] = h;
        }
        __syncthreads();
    }
}

// ---------------- final linear + gather ----------------
// y[trace*32 + k] = W_lin . h2[k][trace][:] + b_lin   (warp per output)
__global__ void __launch_bounds__(256)
final_gather(const float* __restrict__ W_lin,
             const float* __restrict__ b_lin,
             float* __restrict__ y)
{
    int warp = (blockIdx.x * blockDim.x + threadIdx.x) >> 5;
    int lane = threadIdx.x & 31;
    if (warp >= BB * TT) return;
    int trace = warp >> 5;      // /32
    int k     = warp & 31;
    const float* hrow = g_h2 + (k * BB + trace) * HID;

    float s = 0.0f;
#pragma unroll
    for (int h = 0; h < HID; h += 32) s += hrow[h + lane] * W_lin[h + lane];
#pragma unroll
    for (int o = 16; o > 0; o >>= 1) s += __shfl_xor_sync(0xFFFFFFFFu, s, o);
    if (lane == 0) y[warp] = s + b_lin[0];
}

// ---------------- launch ----------------
extern "C" void kernel_launch(void* const* d_in, const int* in_sizes, int n_in,
                              void* d_out, int out_size)
{
    const float* input = (const float*)d_in[0];
    const float* W_ih0 = (const float*)d_in[1];
    const float* W_hh0 = (const float*)d_in[2];
    const float* b_ih0 = (const float*)d_in[3];
    const float* b_hh0 = (const float*)d_in[4];
    const float* W_ih1 = (const float*)d_in[5];
    const float* W_hh1 = (const float*)d_in[6];
    const float* b_ih1 = (const float*)d_in[7];
    const float* b_hh1 = (const float*)d_in[8];
    const float* W_lin = (const float*)d_in[9];
    const float* b_lin = (const float*)d_in[10];
    float* y = (float*)d_out;

    const int smem = (2 * HID + G4 + G4 * WPAD) * (int)sizeof(float); // 142336 B
    cudaFuncSetAttribute(lstm_scan, cudaFuncAttributeMaxDynamicSharedMemorySize, smem);

    // layer 0 input projection: P = X . W_ih0^T + b_ih0 + b_hh0
    xproj_gemm<64, true><<<dim3(64, 8), 256>>>(input, W_ih0, b_ih0, b_hh0);
    // layer 0 recurrence -> g_h1
    lstm_scan<<<BB, 512, smem>>>(W_hh0, 0);
    // layer 1 input projection: P = h1 . W_ih1^T + b_ih1 + b_hh1
    xproj_gemm<128, false><<<dim3(64, 8), 256>>>(nullptr, W_ih1, b_ih1, b_hh1);
    // layer 1 recurrence -> g_h2
    lstm_scan<<<BB, 512, smem>>>(W_hh1, 1);
    // output head + prefix gather
    final_gather<<<(BB * TT * 32) / 256, 256>>>(W_lin, b_lin, y);
}

// round 8
// speedup vs baseline: 1.0045x; 1.0045x over previous
#include <cuda_runtime.h>
#include <math.h>

#define TT   32     // timesteps
#define BB   128    // traces (collapsed batch)
#define HID  128
#define G4   512    // 4*HID
#define WPAD 68     // smem weight row stride (floats), 16B-aligned, conflict-minimal

// ---------------- scratch (static device globals; no allocation) ----------------
__device__ float g_P [TT * BB * G4];   // x-projection + biases, [t][trace][512]  (8 MB, reused for both layers)
__device__ float g_h1[TT * BB * HID];  // layer-0 hidden stream [t][trace][128]
__device__ float g_h2[TT * BB * HID];  // layer-1 hidden stream

__device__ __forceinline__ float sigf(float x) { return 1.0f / (1.0f + expf(-x)); }

// ---------------- x-projection GEMM ----------------
// C[m][n] = sum_k A[arow(m)][k] * W[n][k] + b1[n] + b2[n]
// m = t*128 + trace ; REMAP: arow = trace*32 + t (layer-0 input layout), else arow = m.
template<int KTOT, bool REMAP>
__global__ void __launch_bounds__(256)
xproj_gemm(const float* __restrict__ Aext,
           const float* __restrict__ W,
           const float* __restrict__ b1,
           const float* __restrict__ b2)
{
    __shared__ float As[64][65];
    __shared__ float Ws[64][65];

    const float* A = REMAP ? Aext : g_h1;   // layer-1 consumes g_h1 directly

    const int m0 = blockIdx.x * 64;
    const int n0 = blockIdx.y * 64;
    const int tx = threadIdx.x;
    const int trow = (tx >> 4) * 4;   // 0..60
    const int tcol = (tx & 15) * 4;   // 0..60

    float acc[4][4];
#pragma unroll
    for (int i = 0; i < 4; i++)
#pragma unroll
        for (int j = 0; j < 4; j++) acc[i][j] = 0.0f;

    for (int kc = 0; kc < KTOT; kc += 64) {
        // load A tile 64x64
#pragma unroll
        for (int it = 0; it < 4; it++) {
            int i  = tx + it * 256;
            int r  = i >> 4;
            int c4 = (i & 15) << 2;
            int m  = m0 + r;
            int arow = REMAP ? ((m & 127) * TT + (m >> 7)) : m;
            float4 v = *(const float4*)(A + arow * KTOT + kc + c4);
            As[r][c4 + 0] = v.x; As[r][c4 + 1] = v.y;
            As[r][c4 + 2] = v.z; As[r][c4 + 3] = v.w;
        }
        // load W tile 64x64
#pragma unroll
        for (int it = 0; it < 4; it++) {
            int i  = tx + it * 256;
            int r  = i >> 4;
            int c4 = (i & 15) << 2;
            float4 v = *(const float4*)(W + (n0 + r) * KTOT + kc + c4);
            Ws[r][c4 + 0] = v.x; Ws[r][c4 + 1] = v.y;
            Ws[r][c4 + 2] = v.z; Ws[r][c4 + 3] = v.w;
        }
        __syncthreads();

#pragma unroll
        for (int k = 0; k < 64; k++) {
            float a0 = As[trow + 0][k], a1 = As[trow + 1][k];
            float a2 = As[trow + 2][k], a3 = As[trow + 3][k];
            float w0 = Ws[tcol + 0][k], w1 = Ws[tcol + 1][k];
            float w2 = Ws[tcol + 2][k], w3 = Ws[tcol + 3][k];
            acc[0][0] += a0 * w0; acc[0][1] += a0 * w1; acc[0][2] += a0 * w2; acc[0][3] += a0 * w3;
            acc[1][0] += a1 * w0; acc[1][1] += a1 * w1; acc[1][2] += a1 * w2; acc[1][3] += a1 * w3;
            acc[2][0] += a2 * w0; acc[2][1] += a2 * w1; acc[2][2] += a2 * w2; acc[2][3] += a2 * w3;
            acc[3][0] += a3 * w0; acc[3][1] += a3 * w1; acc[3][2] += a3 * w2; acc[3][3] += a3 * w3;
        }
        __syncthreads();
    }

    float bias[4];
#pragma unroll
    for (int j = 0; j < 4; j++) {
        int n = n0 + tcol + j;
        bias[j] = b1[n] + b2[n];
    }
#pragma unroll
    for (int i = 0; i < 4; i++) {
        int m = m0 + trow + i;
        float4 o;
        o.x = acc[i][0] + bias[0];
        o.y = acc[i][1] + bias[1];
        o.z = acc[i][2] + bias[2];
        o.w = acc[i][3] + bias[3];
        *(float4*)(g_P + m * G4 + n0 + tcol) = o;
    }
}

// ---------------- recurrent scan: one CTA per trace ----------------
// 512 threads. Thread tid owns gate row tid: W_hh[tid][0:64] in registers,
// W_hh[tid][64:128] in shared. h double-buffered in shared. c lives in
// registers of threads 0..127. Reads g_P, writes g_h1 (layer 0) or g_h2.
__global__ void __launch_bounds__(512, 1)
lstm_scan(const float* __restrict__ W_hh, int layer)
{
    extern __shared__ float sm[];
    float* h_sm = sm;                 // 2 * 128
    float* gate = sm + 2 * HID;       // 512
    float* Wsm  = sm + 2 * HID + G4;  // 512 * WPAD

    const int tid   = threadIdx.x;    // gate row 0..511
    const int trace = blockIdx.x;     // 0..127
    float* __restrict__ h_out = layer ? g_h2 : g_h1;

    // ---- preload weights ----
    float w[64];
    const float4* wrow = (const float4*)(W_hh + tid * HID);
#pragma unroll
    for (int k4 = 0; k4 < 16; k4++) {
        float4 v = wrow[k4];
        w[4 * k4 + 0] = v.x; w[4 * k4 + 1] = v.y;
        w[4 * k4 + 2] = v.z; w[4 * k4 + 3] = v.w;
    }
#pragma unroll
    for (int k4 = 0; k4 < 16; k4++) {
        float4 v = wrow[16 + k4];
        *(float4*)&Wsm[tid * WPAD + 4 * k4] = v;
    }
    if (tid < 2 * HID) h_sm[tid] = 0.0f;
    float c = 0.0f;
    __syncthreads();

    const float* __restrict__ Pb = g_P + trace * G4 + tid;

    for (int t = 0; t < TT; t++) {
        const float* hb = h_sm + (t & 1) * HID;   // h_{t-1}
        float acc0 = Pb[t * BB * G4];             // x-proj + biases
        float acc1 = 0.0f, acc2 = 0.0f, acc3 = 0.0f;

#pragma unroll
        for (int k4 = 0; k4 < 16; k4++) {         // K = 0..63 (register weights)
            float4 hv = *(const float4*)(hb + 4 * k4);
            acc0 += w[4 * k4 + 0] * hv.x;
            acc1 += w[4 * k4 + 1] * hv.y;
            acc2 += w[4 * k4 + 2] * hv.z;
            acc3 += w[4 * k4 + 3] * hv.w;
        }
#pragma unroll
        for (int k4 = 0; k4 < 16; k4++) {         // K = 64..127 (smem weights)
            float4 hv = *(const float4*)(hb + 64 + 4 * k4);
            float4 wv = *(const float4*)&Wsm[tid * WPAD + 4 * k4];
            acc0 += wv.x * hv.x;
            acc1 += wv.y * hv.y;
            acc2 += wv.z * hv.z;
            acc3 += wv.w * hv.w;
        }
        gate[tid] = (acc0 + acc1) + (acc2 + acc3);
        __syncthreads();

        if (tid < HID) {
            float ig = sigf(gate[tid]);
            float fg = sigf(gate[HID + tid]);
            float gg = tanhf(gate[2 * HID + tid]);
            float og = sigf(gate[3 * HID + tid]);
            c = fg * c + ig * gg;
            float h = og * tanhf(c);
            h_sm[((t + 1) & 1) * HID + tid] = h;
            h_out[(t * BB + trace) * HID + tid] = h;
        }
        __syncthreads();
    }
}

// ---------------- final linear + gather ----------------
// y[trace*32 + k] = W_lin . h2[k][trace][:] + b_lin   (warp per output)
__global__ void __launch_bounds__(256)
final_gather(const float* __restrict__ W_lin,
             const float* __restrict__ b_lin,
             float* __restrict__ y)
{
    int warp = (blockIdx.x * blockDim.x + threadIdx.x) >> 5;
    int lane = threadIdx.x & 31;
    if (warp >= BB * TT) return;
    int trace = warp >> 5;      // /32
    int k     = warp & 31;
    const float* hrow = g_h2 + (k * BB + trace) * HID;

    float s = 0.0f;
#pragma unroll
    for (int h = 0; h < HID; h += 32) s += hrow[h + lane] * W_lin[h + lane];
#pragma unroll
    for (int o = 16; o > 0; o >>= 1) s += __shfl_xor_sync(0xFFFFFFFFu, s, o);
    if (lane == 0) y[warp] = s + b_lin[0];
}

// ---------------- launch ----------------
extern "C" void kernel_launch(void* const* d_in, const int* in_sizes, int n_in,
                              void* d_out, int out_size)
{
    const float* input = (const float*)d_in[0];
    const float* W_ih0 = (const float*)d_in[1];
    const float* W_hh0 = (const float*)d_in[2];
    const float* b_ih0 = (const float*)d_in[3];
    const float* b_hh0 = (const float*)d_in[4];
    const float* W_ih1 = (const float*)d_in[5];
    const float* W_hh1 = (const float*)d_in[6];
    const float* b_ih1 = (const float*)d_in[7];
    const float* b_hh1 = (const float*)d_in[8];
    const float* W_lin = (const float*)d_in[9];
    const float* b_lin = (const float*)d_in[10];
    float* y = (float*)d_out;

    const int smem = (2 * HID + G4 + G4 * WPAD) * (int)sizeof(float); // 142336 B
    cudaFuncSetAttribute(lstm_scan, cudaFuncAttributeMaxDynamicSharedMemorySize, smem);

    // layer 0 input projection: P = X . W_ih0^T + b_ih0 + b_hh0
    xproj_gemm<64, true><<<dim3(64, 8), 256>>>(input, W_ih0, b_ih0, b_hh0);
    // layer 0 recurrence -> g_h1
    lstm_scan<<<BB, 512, smem>>>(W_hh0, 0);
    // layer 1 input projection: P = h1 . W_ih1^T + b_ih1 + b_hh1
    xproj_gemm<128, false><<<dim3(64, 8), 256>>>(nullptr, W_ih1, b_ih1, b_hh1);
    // layer 1 recurrence -> g_h2
    lstm_scan<<<BB, 512, smem>>>(W_hh1, 1);
    // output head + prefix gather
    final_gather<<<(BB * TT * 32) / 256, 256>>>(W_lin, b_lin, y);
}

// round 9
// speedup vs baseline: 1.2616x; 1.2560x over previous
#include <cuda_runtime.h>
#include <math.h>

#define TT   32     // timesteps
#define BB   128    // traces (collapsed batch)
#define HID  128
#define G4   512    // 4*HID
#define WoSTR 36    // smem o-gate weight row stride (floats): 144B, conflict-free LDS.128

// ---------------- scratch (static device globals; no allocation) ----------------
__device__ float g_P [TT * BB * G4];   // x-projection + biases, [t][trace][512]
__device__ float g_h1[TT * BB * HID];  // layer-0 hidden stream [t][trace][128]
__device__ float g_h2[TT * BB * HID];  // layer-1 hidden stream

// ---------------- packed f32x2 + fast activation helpers ----------------
__device__ __forceinline__ unsigned long long fma2(unsigned long long a,
                                                   unsigned long long b,
                                                   unsigned long long c) {
    unsigned long long d;
    asm("fma.rn.f32x2 %0, %1, %2, %3;" : "=l"(d) : "l"(a), "l"(b), "l"(c));
    return d;
}
__device__ __forceinline__ float f2sum(unsigned long long a) {
    float lo, hi;
    asm("mov.b64 {%0, %1}, %2;" : "=f"(lo), "=f"(hi) : "l"(a));
    return lo + hi;
}
__device__ __forceinline__ float ex2a(float x) { float y; asm("ex2.approx.f32 %0, %1;" : "=f"(y) : "f"(x)); return y; }
__device__ __forceinline__ float rcpa(float x) { float y; asm("rcp.approx.f32 %0, %1;" : "=f"(y) : "f"(x)); return y; }
// sigmoid(x) = 1/(1+2^(-x*log2e)) ; tanh(x) = 2*sigmoid(2x)-1
__device__ __forceinline__ float sigf(float x)   { return rcpa(1.0f + ex2a(-1.44269504f * x)); }
__device__ __forceinline__ float tanhfa(float x) { return 2.0f * rcpa(1.0f + ex2a(-2.88539008f * x)) - 1.0f; }

// ---------------- x-projection GEMM (unchanged) ----------------
template<int KTOT, bool REMAP>
__global__ void __launch_bounds__(256)
xproj_gemm(const float* __restrict__ Aext,
           const float* __restrict__ W,
           const float* __restrict__ b1,
           const float* __restrict__ b2)
{
    __shared__ float As[64][65];
    __shared__ float Ws[64][65];

    const float* A = REMAP ? Aext : g_h1;

    const int m0 = blockIdx.x * 64;
    const int n0 = blockIdx.y * 64;
    const int tx = threadIdx.x;
    const int trow = (tx >> 4) * 4;
    const int tcol = (tx & 15) * 4;

    float acc[4][4];
#pragma unroll
    for (int i = 0; i < 4; i++)
#pragma unroll
        for (int j = 0; j < 4; j++) acc[i][j] = 0.0f;

    for (int kc = 0; kc < KTOT; kc += 64) {
#pragma unroll
        for (int it = 0; it < 4; it++) {
            int i  = tx + it * 256;
            int r  = i >> 4;
            int c4 = (i & 15) << 2;
            int m  = m0 + r;
            int arow = REMAP ? ((m & 127) * TT + (m >> 7)) : m;
            float4 v = *(const float4*)(A + arow * KTOT + kc + c4);
            As[r][c4 + 0] = v.x; As[r][c4 + 1] = v.y;
            As[r][c4 + 2] = v.z; As[r][c4 + 3] = v.w;
        }
#pragma unroll
        for (int it = 0; it < 4; it++) {
            int i  = tx + it * 256;
            int r  = i >> 4;
            int c4 = (i & 15) << 2;
            float4 v = *(const float4*)(W + (n0 + r) * KTOT + kc + c4);
            Ws[r][c4 + 0] = v.x; Ws[r][c4 + 1] = v.y;
            Ws[r][c4 + 2] = v.z; Ws[r][c4 + 3] = v.w;
        }
        __syncthreads();

#pragma unroll
        for (int k = 0; k < 64; k++) {
            float a0 = As[trow + 0][k], a1 = As[trow + 1][k];
            float a2 = As[trow + 2][k], a3 = As[trow + 3][k];
            float w0 = Ws[tcol + 0][k], w1 = Ws[tcol + 1][k];
            float w2 = Ws[tcol + 2][k], w3 = Ws[tcol + 3][k];
            acc[0][0] += a0 * w0; acc[0][1] += a0 * w1; acc[0][2] += a0 * w2; acc[0][3] += a0 * w3;
            acc[1][0] += a1 * w0; acc[1][1] += a1 * w1; acc[1][2] += a1 * w2; acc[1][3] += a1 * w3;
            acc[2][0] += a2 * w0; acc[2][1] += a2 * w1; acc[2][2] += a2 * w2; acc[2][3] += a2 * w3;
            acc[3][0] += a3 * w0; acc[3][1] += a3 * w1; acc[3][2] += a3 * w2; acc[3][3] += a3 * w3;
        }
        __syncthreads();
    }

    float bias[4];
#pragma unroll
    for (int j = 0; j < 4; j++) {
        int n = n0 + tcol + j;
        bias[j] = b1[n] + b2[n];
    }
#pragma unroll
    for (int i = 0; i < 4; i++) {
        int m = m0 + trow + i;
        float4 o;
        o.x = acc[i][0] + bias[0];
        o.y = acc[i][1] + bias[1];
        o.z = acc[i][2] + bias[2];
        o.w = acc[i][3] + bias[3];
        *(float4*)(g_P + m * G4 + n0 + tcol) = o;
    }
}

// ---------------- recurrent scan: one CTA per trace, quad-per-j layout ----------------
// 512 threads. Lane quad (l&3)=s owns K-slice [32s,32s+32); (warp, l>>2) -> j in 0..127.
// Each thread accumulates all 4 gates for its (j, s) slice: i/f/g weights in registers
// (96 floats, pre-rotated for bank-conflict-free h loads), o weights in smem.
// Gates completed via 2 shfl_xor; activations quad-redundant; ONE barrier per step.
__global__ void __launch_bounds__(512, 1)
lstm_scan(const float* __restrict__ W_hh, int layer)
{
    extern __shared__ float sm[];
    float* hbuf = sm;            // 2 * 128 floats (double buffer)
    float* Wo   = sm + 256;      // 512 * WoSTR floats

    const int tid   = threadIdx.x;
    const int w     = tid >> 5;
    const int l     = tid & 31;
    const int j     = w * 8 + (l >> 2);   // h index 0..127
    const int s     = l & 3;              // K-slice
    const int trace = blockIdx.x;
    float* __restrict__ h_out = layer ? g_h2 : g_h1;

    // ---- preload weights (pre-rotated: slot i holds k-chunk (i+2s)&7 of slice s) ----
    unsigned long long wr[48];            // gates i,f,g : 96 floats in registers
#pragma unroll
    for (int g = 0; g < 3; g++) {
#pragma unroll
        for (int i = 0; i < 8; i++) {
            int idx = (i + 2 * s) & 7;
            ulonglong2 v = *(const ulonglong2*)(W_hh + (g * HID + j) * HID + 32 * s + 4 * idx);
            wr[g * 16 + 2 * i]     = v.x;
            wr[g * 16 + 2 * i + 1] = v.y;
        }
    }
    float* wop = Wo + tid * WoSTR;        // gate o : 32 floats in smem, pre-rotated
#pragma unroll
    for (int i = 0; i < 8; i++) {
        int idx = (i + 2 * s) & 7;
        ulonglong2 v = *(const ulonglong2*)(W_hh + (3 * HID + j) * HID + 32 * s + 4 * idx);
        *(ulonglong2*)(wop + 4 * i) = v;
    }
    if (tid < HID) hbuf[tid] = 0.0f;
    float c = 0.0f;
    __syncthreads();

    const float* __restrict__ pP = g_P + trace * G4 + j;

    for (int t = 0; t < TT; t++) {
        // early-issue x-proj terms (independent of h; hidden under K-loop)
        const float* pt = pP + t * BB * G4;
        float p0 = pt[0];
        float p1 = pt[HID];
        float p2 = pt[2 * HID];
        float p3 = pt[3 * HID];

        const float* hb = hbuf + (t & 1) * HID + 32 * s;
        unsigned long long a0 = 0ull, a1 = 0ull, a2 = 0ull, a3 = 0ull;
#pragma unroll
        for (int i = 0; i < 8; i++) {
            int idx = (i + 2 * s) & 7;                          // bank rotation per slice
            ulonglong2 hv = *(const ulonglong2*)(hb + 4 * idx); // 4 h values as 2x f32x2
            ulonglong2 wv = *(const ulonglong2*)(wop + 4 * i);  // o-gate weights
            a0 = fma2(wr[0 * 16 + 2 * i],     hv.x, a0);
            a0 = fma2(wr[0 * 16 + 2 * i + 1], hv.y, a0);
            a1 = fma2(wr[1 * 16 + 2 * i],     hv.x, a1);
            a1 = fma2(wr[1 * 16 + 2 * i + 1], hv.y, a1);
            a2 = fma2(wr[2 * 16 + 2 * i],     hv.x, a2);
            a2 = fma2(wr[2 * 16 + 2 * i + 1], hv.y, a2);
            a3 = fma2(wv.x, hv.x, a3);
            a3 = fma2(wv.y, hv.y, a3);
        }
        // complete the 128-wide dots across the quad (s = 0..3)
        float v0 = f2sum(a0), v1 = f2sum(a1), v2 = f2sum(a2), v3 = f2sum(a3);
        v0 += __shfl_xor_sync(0xFFFFFFFFu, v0, 1);
        v1 += __shfl_xor_sync(0xFFFFFFFFu, v1, 1);
        v2 += __shfl_xor_sync(0xFFFFFFFFu, v2, 1);
        v3 += __shfl_xor_sync(0xFFFFFFFFu, v3, 1);
        v0 += __shfl_xor_sync(0xFFFFFFFFu, v0, 2);
        v1 += __shfl_xor_sync(0xFFFFFFFFu, v1, 2);
        v2 += __shfl_xor_sync(0xFFFFFFFFu, v2, 2);
        v3 += __shfl_xor_sync(0xFFFFFFFFu, v3, 2);

        // activations (quad-redundant; identical FP sequence -> identical c in all 4 lanes)
        float ig = sigf(v0 + p0);
        float fg = sigf(v1 + p1);
        float gg = tanhfa(v2 + p2);
        float og = sigf(v3 + p3);
        c = fg * c + ig * gg;
        float h = og * tanhfa(c);

        if (s == 0) {
            hbuf[((t + 1) & 1) * HID + j] = h;
            h_out[(t * BB + trace) * HID + j] = h;
        }
        __syncthreads();
    }
}

// ---------------- final linear + gather (unchanged) ----------------
__global__ void __launch_bounds__(256)
final_gather(const float* __restrict__ W_lin,
             const float* __restrict__ b_lin,
             float* __restrict__ y)
{
    int warp = (blockIdx.x * blockDim.x + threadIdx.x) >> 5;
    int lane = threadIdx.x & 31;
    if (warp >= BB * TT) return;
    int trace = warp >> 5;
    int k     = warp & 31;
    const float* hrow = g_h2 + (k * BB + trace) * HID;

    float sv = 0.0f;
#pragma unroll
    for (int h = 0; h < HID; h += 32) sv += hrow[h + lane] * W_lin[h + lane];
#pragma unroll
    for (int o = 16; o > 0; o >>= 1) sv += __shfl_xor_sync(0xFFFFFFFFu, sv, o);
    if (lane == 0) y[warp] = sv + b_lin[0];
}

// ---------------- launch ----------------
extern "C" void kernel_launch(void* const* d_in, const int* in_sizes, int n_in,
                              void* d_out, int out_size)
{
    const float* input = (const float*)d_in[0];
    const float* W_ih0 = (const float*)d_in[1];
    const float* W_hh0 = (const float*)d_in[2];
    const float* b_ih0 = (const float*)d_in[3];
    const float* b_hh0 = (const float*)d_in[4];
    const float* W_ih1 = (const float*)d_in[5];
    const float* W_hh1 = (const float*)d_in[6];
    const float* b_ih1 = (const float*)d_in[7];
    const float* b_hh1 = (const float*)d_in[8];
    const float* W_lin = (const float*)d_in[9];
    const float* b_lin = (const float*)d_in[10];
    float* y = (float*)d_out;

    const int smem = (256 + G4 * WoSTR) * (int)sizeof(float); // 74,752 B
    cudaFuncSetAttribute(lstm_scan, cudaFuncAttributeMaxDynamicSharedMemorySize, smem);

    xproj_gemm<64, true><<<dim3(64, 8), 256>>>(input, W_ih0, b_ih0, b_hh0);
    lstm_scan<<<BB, 512, smem>>>(W_hh0, 0);
    xproj_gemm<128, false><<<dim3(64, 8), 256>>>(nullptr, W_ih1, b_ih1, b_hh1);
    lstm_scan<<<BB, 512, smem>>>(W_hh1, 1);
    final_gather<<<(BB * TT * 32) / 256, 256>>>(W_lin, b_lin, y);
}

// round 10
// speedup vs baseline: 1.2649x; 1.0025x over previous
#include <cuda_runtime.h>
#include <math.h>

#define TT   32     // timesteps
#define BB   128    // traces (collapsed batch)
#define HID  128
#define G4   512    // 4*HID
#define WoSTR 36    // smem o-gate weight row stride (floats): 144B, conflict-free LDS.128

// ---------------- scratch (static device globals; no allocation) ----------------
__device__ float g_P [TT * BB * G4];   // x-projection + biases, [t][trace][512]
__device__ float g_h1[TT * BB * HID];  // layer-0 hidden stream [t][trace][128]
__device__ float g_h2[TT * BB * HID];  // layer-1 hidden stream

// ---------------- packed f32x2 + fast activation helpers ----------------
__device__ __forceinline__ unsigned long long fma2(unsigned long long a,
                                                   unsigned long long b,
                                                   unsigned long long c) {
    unsigned long long d;
    asm("fma.rn.f32x2 %0, %1, %2, %3;" : "=l"(d) : "l"(a), "l"(b), "l"(c));
    return d;
}
__device__ __forceinline__ float f2sum(unsigned long long a) {
    float lo, hi;
    asm("mov.b64 {%0, %1}, %2;" : "=f"(lo), "=f"(hi) : "l"(a));
    return lo + hi;
}
__device__ __forceinline__ float ex2a(float x) { float y; asm("ex2.approx.f32 %0, %1;" : "=f"(y) : "f"(x)); return y; }
__device__ __forceinline__ float rcpa(float x) { float y; asm("rcp.approx.f32 %0, %1;" : "=f"(y) : "f"(x)); return y; }
// sigmoid(x) = 1/(1+2^(-x*log2e)) ; tanh(x) = 2*sigmoid(2x)-1
__device__ __forceinline__ float sigf(float x)   { return rcpa(1.0f + ex2a(-1.44269504f * x)); }
__device__ __forceinline__ float tanhfa(float x) { return 2.0f * rcpa(1.0f + ex2a(-2.88539008f * x)) - 1.0f; }

// ---------------- x-projection GEMM (unchanged) ----------------
template<int KTOT, bool REMAP>
__global__ void __launch_bounds__(256)
xproj_gemm(const float* __restrict__ Aext,
           const float* __restrict__ W,
           const float* __restrict__ b1,
           const float* __restrict__ b2)
{
    __shared__ float As[64][65];
    __shared__ float Ws[64][65];

    const float* A = REMAP ? Aext : g_h1;

    const int m0 = blockIdx.x * 64;
    const int n0 = blockIdx.y * 64;
    const int tx = threadIdx.x;
    const int trow = (tx >> 4) * 4;
    const int tcol = (tx & 15) * 4;

    float acc[4][4];
#pragma unroll
    for (int i = 0; i < 4; i++)
#pragma unroll
        for (int j = 0; j < 4; j++) acc[i][j] = 0.0f;

    for (int kc = 0; kc < KTOT; kc += 64) {
#pragma unroll
        for (int it = 0; it < 4; it++) {
            int i  = tx + it * 256;
            int r  = i >> 4;
            int c4 = (i & 15) << 2;
            int m  = m0 + r;
            int arow = REMAP ? ((m & 127) * TT + (m >> 7)) : m;
            float4 v = *(const float4*)(A + arow * KTOT + kc + c4);
            As[r][c4 + 0] = v.x; As[r][c4 + 1] = v.y;
            As[r][c4 + 2] = v.z; As[r][c4 + 3] = v.w;
        }
#pragma unroll
        for (int it = 0; it < 4; it++) {
            int i  = tx + it * 256;
            int r  = i >> 4;
            int c4 = (i & 15) << 2;
            float4 v = *(const float4*)(W + (n0 + r) * KTOT + kc + c4);
            Ws[r][c4 + 0] = v.x; Ws[r][c4 + 1] = v.y;
            Ws[r][c4 + 2] = v.z; Ws[r][c4 + 3] = v.w;
        }
        __syncthreads();

#pragma unroll
        for (int k = 0; k < 64; k++) {
            float a0 = As[trow + 0][k], a1 = As[trow + 1][k];
            float a2 = As[trow + 2][k], a3 = As[trow + 3][k];
            float w0 = Ws[tcol + 0][k], w1 = Ws[tcol + 1][k];
            float w2 = Ws[tcol + 2][k], w3 = Ws[tcol + 3][k];
            acc[0][0] += a0 * w0; acc[0][1] += a0 * w1; acc[0][2] += a0 * w2; acc[0][3] += a0 * w3;
            acc[1][0] += a1 * w0; acc[1][1] += a1 * w1; acc[1][2] += a1 * w2; acc[1][3] += a1 * w3;
            acc[2][0] += a2 * w0; acc[2][1] += a2 * w1; acc[2][2] += a2 * w2; acc[2][3] += a2 * w3;
            acc[3][0] += a3 * w0; acc[3][1] += a3 * w1; acc[3][2] += a3 * w2; acc[3][3] += a3 * w3;
        }
        __syncthreads();
    }

    float bias[4];
#pragma unroll
    for (int j = 0; j < 4; j++) {
        int n = n0 + tcol + j;
        bias[j] = b1[n] + b2[n];
    }
#pragma unroll
    for (int i = 0; i < 4; i++) {
        int m = m0 + trow + i;
        float4 o;
        o.x = acc[i][0] + bias[0];
        o.y = acc[i][1] + bias[1];
        o.z = acc[i][2] + bias[2];
        o.w = acc[i][3] + bias[3];
        *(float4*)(g_P + m * G4 + n0 + tcol) = o;
    }
}

// ---------------- recurrent scan: one CTA per trace, quad-per-j layout ----------------
// 512 threads. Lane quad (l&3)=s owns K-slice [32s,32s+32); (warp, l>>2) -> j in 0..127.
// Each thread accumulates all 4 gates for its (j, s) slice: i/f/g weights in registers
// (96 floats, pre-rotated for bank-conflict-free h loads), o weights in smem.
// Gates completed via 2 shfl_xor; activations quad-redundant; ONE barrier per step.
__global__ void __launch_bounds__(512, 1)
lstm_scan(const float* __restrict__ W_hh, int layer)
{
    extern __shared__ float sm[];
    float* hbuf = sm;            // 2 * 128 floats (double buffer)
    float* Wo   = sm + 256;      // 512 * WoSTR floats

    const int tid   = threadIdx.x;
    const int w     = tid >> 5;
    const int l     = tid & 31;
    const int j     = w * 8 + (l >> 2);   // h index 0..127
    const int s     = l & 3;              // K-slice
    const int trace = blockIdx.x;
    float* __restrict__ h_out = layer ? g_h2 : g_h1;

    // ---- preload weights (pre-rotated: slot i holds k-chunk (i+2s)&7 of slice s) ----
    unsigned long long wr[48];            // gates i,f,g : 96 floats in registers
#pragma unroll
    for (int g = 0; g < 3; g++) {
#pragma unroll
        for (int i = 0; i < 8; i++) {
            int idx = (i + 2 * s) & 7;
            ulonglong2 v = *(const ulonglong2*)(W_hh + (g * HID + j) * HID + 32 * s + 4 * idx);
            wr[g * 16 + 2 * i]     = v.x;
            wr[g * 16 + 2 * i + 1] = v.y;
        }
    }
    float* wop = Wo + tid * WoSTR;        // gate o : 32 floats in smem, pre-rotated
#pragma unroll
    for (int i = 0; i < 8; i++) {
        int idx = (i + 2 * s) & 7;
        ulonglong2 v = *(const ulonglong2*)(W_hh + (3 * HID + j) * HID + 32 * s + 4 * idx);
        *(ulonglong2*)(wop + 4 * i) = v;
    }
    if (tid < HID) hbuf[tid] = 0.0f;
    float c = 0.0f;
    __syncthreads();

    const float* __restrict__ pP = g_P + trace * G4 + j;

    for (int t = 0; t < TT; t++) {
        // early-issue x-proj terms (independent of h; hidden under K-loop)
        const float* pt = pP + t * BB * G4;
        float p0 = pt[0];
        float p1 = pt[HID];
        float p2 = pt[2 * HID];
        float p3 = pt[3 * HID];

        const float* hb = hbuf + (t & 1) * HID + 32 * s;
        unsigned long long a0 = 0ull, a1 = 0ull, a2 = 0ull, a3 = 0ull;
#pragma unroll
        for (int i = 0; i < 8; i++) {
            int idx = (i + 2 * s) & 7;                          // bank rotation per slice
            ulonglong2 hv = *(const ulonglong2*)(hb + 4 * idx); // 4 h values as 2x f32x2
            ulonglong2 wv = *(const ulonglong2*)(wop + 4 * i);  // o-gate weights
            a0 = fma2(wr[0 * 16 + 2 * i],     hv.x, a0);
            a0 = fma2(wr[0 * 16 + 2 * i + 1], hv.y, a0);
            a1 = fma2(wr[1 * 16 + 2 * i],     hv.x, a1);
            a1 = fma2(wr[1 * 16 + 2 * i + 1], hv.y, a1);
            a2 = fma2(wr[2 * 16 + 2 * i],     hv.x, a2);
            a2 = fma2(wr[2 * 16 + 2 * i + 1], hv.y, a2);
            a3 = fma2(wv.x, hv.x, a3);
            a3 = fma2(wv.y, hv.y, a3);
        }
        // complete the 128-wide dots across the quad (s = 0..3)
        float v0 = f2sum(a0), v1 = f2sum(a1), v2 = f2sum(a2), v3 = f2sum(a3);
        v0 += __shfl_xor_sync(0xFFFFFFFFu, v0, 1);
        v1 += __shfl_xor_sync(0xFFFFFFFFu, v1, 1);
        v2 += __shfl_xor_sync(0xFFFFFFFFu, v2, 1);
        v3 += __shfl_xor_sync(0xFFFFFFFFu, v3, 1);
        v0 += __shfl_xor_sync(0xFFFFFFFFu, v0, 2);
        v1 += __shfl_xor_sync(0xFFFFFFFFu, v1, 2);
        v2 += __shfl_xor_sync(0xFFFFFFFFu, v2, 2);
        v3 += __shfl_xor_sync(0xFFFFFFFFu, v3, 2);

        // activations (quad-redundant; identical FP sequence -> identical c in all 4 lanes)
        float ig = sigf(v0 + p0);
        float fg = sigf(v1 + p1);
        float gg = tanhfa(v2 + p2);
        float og = sigf(v3 + p3);
        c = fg * c + ig * gg;
        float h = og * tanhfa(c);

        if (s == 0) {
            hbuf[((t + 1) & 1) * HID + j] = h;
            h_out[(t * BB + trace) * HID + j] = h;
        }
        __syncthreads();
    }
}

// ---------------- final linear + gather (unchanged) ----------------
__global__ void __launch_bounds__(256)
final_gather(const float* __restrict__ W_lin,
             const float* __restrict__ b_lin,
             float* __restrict__ y)
{
    int warp = (blockIdx.x * blockDim.x + threadIdx.x) >> 5;
    int lane = threadIdx.x & 31;
    if (warp >= BB * TT) return;
    int trace = warp >> 5;
    int k     = warp & 31;
    const float* hrow = g_h2 + (k * BB + trace) * HID;

    float sv = 0.0f;
#pragma unroll
    for (int h = 0; h < HID; h += 32) sv += hrow[h + lane] * W_lin[h + lane];
#pragma unroll
    for (int o = 16; o > 0; o >>= 1) sv += __shfl_xor_sync(0xFFFFFFFFu, sv, o);
    if (lane == 0) y[warp] = sv + b_lin[0];
}

// ---------------- launch ----------------
extern "C" void kernel_launch(void* const* d_in, const int* in_sizes, int n_in,
                              void* d_out, int out_size)
{
    const float* input = (const float*)d_in[0];
    const float* W_ih0 = (const float*)d_in[1];
    const float* W_hh0 = (const float*)d_in[2];
    const float* b_ih0 = (const float*)d_in[3];
    const float* b_hh0 = (const float*)d_in[4];
    const float* W_ih1 = (const float*)d_in[5];
    const float* W_hh1 = (const float*)d_in[6];
    const float* b_ih1 = (const float*)d_in[7];
    const float* b_hh1 = (const float*)d_in[8];
    const float* W_lin = (const float*)d_in[9];
    const float* b_lin = (const float*)d_in[10];
    float* y = (float*)d_out;

    const int smem = (256 + G4 * WoSTR) * (int)sizeof(float); // 74,752 B
    cudaFuncSetAttribute(lstm_scan, cudaFuncAttributeMaxDynamicSharedMemorySize, smem);

    xproj_gemm<64, true><<<dim3(64, 8), 256>>>(input, W_ih0, b_ih0, b_hh0);
    lstm_scan<<<BB, 512, smem>>>(W_hh0, 0);
    xproj_gemm<128, false><<<dim3(64, 8), 256>>>(nullptr, W_ih1, b_ih1, b_hh1);
    lstm_scan<<<BB, 512, smem>>>(W_hh1, 1);
    final_gather<<<(BB * TT * 32) / 256, 256>>>(W_lin, b_lin, y);
}

// round 11
// speedup vs baseline: 1.2688x; 1.0031x over previous
#include <cuda_runtime.h>
#include <math.h>

#define TT   32     // timesteps
#define BB   128    // traces (collapsed batch)
#define HID  128
#define G4   512    // 4*HID
#define WoSTR 36    // smem o-gate weight row stride (floats): 144B, conflict-free LDS.128

// ---------------- scratch (static device globals; no allocation) ----------------
__device__ float g_P [TT * BB * G4];   // x-projection + biases, [t][trace][512]
__device__ float g_h1[TT * BB * HID];  // layer-0 hidden stream [t][trace][128]
__device__ float g_h2[TT * BB * HID];  // layer-1 hidden stream

// ---------------- packed f32x2 + fast activation helpers ----------------
__device__ __forceinline__ unsigned long long fma2(unsigned long long a,
                                                   unsigned long long b,
                                                   unsigned long long c) {
    unsigned long long d;
    asm("fma.rn.f32x2 %0, %1, %2, %3;" : "=l"(d) : "l"(a), "l"(b), "l"(c));
    return d;
}
__device__ __forceinline__ float f2sum(unsigned long long a) {
    float lo, hi;
    asm("mov.b64 {%0, %1}, %2;" : "=f"(lo), "=f"(hi) : "l"(a));
    return lo + hi;
}
__device__ __forceinline__ float ex2a(float x) { float y; asm("ex2.approx.f32 %0, %1;" : "=f"(y) : "f"(x)); return y; }
__device__ __forceinline__ float rcpa(float x) { float y; asm("rcp.approx.f32 %0, %1;" : "=f"(y) : "f"(x)); return y; }
// sigmoid(x) = 1/(1+2^(-x*log2e)) ; tanh(x) = 2*sigmoid(2x)-1
__device__ __forceinline__ float sigf(float x)   { return rcpa(1.0f + ex2a(-1.44269504f * x)); }
__device__ __forceinline__ float tanhfa(float x) { return 2.0f * rcpa(1.0f + ex2a(-2.88539008f * x)) - 1.0f; }

// ---------------- x-projection GEMM (unchanged) ----------------
template<int KTOT, bool REMAP>
__global__ void __launch_bounds__(256)
xproj_gemm(const float* __restrict__ Aext,
           const float* __restrict__ W,
           const float* __restrict__ b1,
           const float* __restrict__ b2)
{
    __shared__ float As[64][65];
    __shared__ float Ws[64][65];

    const float* A = REMAP ? Aext : g_h1;

    const int m0 = blockIdx.x * 64;
    const int n0 = blockIdx.y * 64;
    const int tx = threadIdx.x;
    const int trow = (tx >> 4) * 4;
    const int tcol = (tx & 15) * 4;

    float acc[4][4];
#pragma unroll
    for (int i = 0; i < 4; i++)
#pragma unroll
        for (int j = 0; j < 4; j++) acc[i][j] = 0.0f;

    for (int kc = 0; kc < KTOT; kc += 64) {
#pragma unroll
        for (int it = 0; it < 4; it++) {
            int i  = tx + it * 256;
            int r  = i >> 4;
            int c4 = (i & 15) << 2;
            int m  = m0 + r;
            int arow = REMAP ? ((m & 127) * TT + (m >> 7)) : m;
            float4 v = *(const float4*)(A + arow * KTOT + kc + c4);
            As[r][c4 + 0] = v.x; As[r][c4 + 1] = v.y;
            As[r][c4 + 2] = v.z; As[r][c4 + 3] = v.w;
        }
#pragma unroll
        for (int it = 0; it < 4; it++) {
            int i  = tx + it * 256;
            int r  = i >> 4;
            int c4 = (i & 15) << 2;
            float4 v = *(const float4*)(W + (n0 + r) * KTOT + kc + c4);
            Ws[r][c4 + 0] = v.x; Ws[r][c4 + 1] = v.y;
            Ws[r][c4 + 2] = v.z; Ws[r][c4 + 3] = v.w;
        }
        __syncthreads();

#pragma unroll
        for (int k = 0; k < 64; k++) {
            float a0 = As[trow + 0][k], a1 = As[trow + 1][k];
            float a2 = As[trow + 2][k], a3 = As[trow + 3][k];
            float w0 = Ws[tcol + 0][k], w1 = Ws[tcol + 1][k];
            float w2 = Ws[tcol + 2][k], w3 = Ws[tcol + 3][k];
            acc[0][0] += a0 * w0; acc[0][1] += a0 * w1; acc[0][2] += a0 * w2; acc[0][3] += a0 * w3;
            acc[1][0] += a1 * w0; acc[1][1] += a1 * w1; acc[1][2] += a1 * w2; acc[1][3] += a1 * w3;
            acc[2][0] += a2 * w0; acc[2][1] += a2 * w1; acc[2][2] += a2 * w2; acc[2][3] += a2 * w3;
            acc[3][0] += a3 * w0; acc[3][1] += a3 * w1; acc[3][2] += a3 * w2; acc[3][3] += a3 * w3;
        }
        __syncthreads();
    }

    float bias[4];
#pragma unroll
    for (int j = 0; j < 4; j++) {
        int n = n0 + tcol + j;
        bias[j] = b1[n] + b2[n];
    }
#pragma unroll
    for (int i = 0; i < 4; i++) {
        int m = m0 + trow + i;
        float4 o;
        o.x = acc[i][0] + bias[0];
        o.y = acc[i][1] + bias[1];
        o.z = acc[i][2] + bias[2];
        o.w = acc[i][3] + bias[3];
        *(float4*)(g_P + m * G4 + n0 + tcol) = o;
    }
}

// ---------------- recurrent scan: one CTA per trace, quad-per-j layout ----------------
// 512 threads. Lane quad (l&3)=s owns K-slice [32s,32s+32); (warp, l>>2) -> j in 0..127.
// Each thread accumulates all 4 gates for its (j, s) slice: i/f/g weights in registers
// (96 floats, pre-rotated for bank-conflict-free h loads), o weights in smem.
// Gates completed via 2 shfl_xor; activations quad-redundant; ONE barrier per step.
__global__ void __launch_bounds__(512, 1)
lstm_scan(const float* __restrict__ W_hh, int layer)
{
    extern __shared__ float sm[];
    float* hbuf = sm;            // 2 * 128 floats (double buffer)
    float* Wo   = sm + 256;      // 512 * WoSTR floats

    const int tid   = threadIdx.x;
    const int w     = tid >> 5;
    const int l     = tid & 31;
    const int j     = w * 8 + (l >> 2);   // h index 0..127
    const int s     = l & 3;              // K-slice
    const int trace = blockIdx.x;
    float* __restrict__ h_out = layer ? g_h2 : g_h1;

    // ---- preload weights (pre-rotated: slot i holds k-chunk (i+2s)&7 of slice s) ----
    unsigned long long wr[48];            // gates i,f,g : 96 floats in registers
#pragma unroll
    for (int g = 0; g < 3; g++) {
#pragma unroll
        for (int i = 0; i < 8; i++) {
            int idx = (i + 2 * s) & 7;
            ulonglong2 v = *(const ulonglong2*)(W_hh + (g * HID + j) * HID + 32 * s + 4 * idx);
            wr[g * 16 + 2 * i]     = v.x;
            wr[g * 16 + 2 * i + 1] = v.y;
        }
    }
    float* wop = Wo + tid * WoSTR;        // gate o : 32 floats in smem, pre-rotated
#pragma unroll
    for (int i = 0; i < 8; i++) {
        int idx = (i + 2 * s) & 7;
        ulonglong2 v = *(const ulonglong2*)(W_hh + (3 * HID + j) * HID + 32 * s + 4 * idx);
        *(ulonglong2*)(wop + 4 * i) = v;
    }
    if (tid < HID) hbuf[tid] = 0.0f;
    float c = 0.0f;
    __syncthreads();

    const float* __restrict__ pP = g_P + trace * G4 + j;

    for (int t = 0; t < TT; t++) {
        // early-issue x-proj terms (independent of h; hidden under K-loop)
        const float* pt = pP + t * BB * G4;
        float p0 = pt[0];
        float p1 = pt[HID];
        float p2 = pt[2 * HID];
        float p3 = pt[3 * HID];

        const float* hb = hbuf + (t & 1) * HID + 32 * s;
        unsigned long long a0 = 0ull, a1 = 0ull, a2 = 0ull, a3 = 0ull;
#pragma unroll
        for (int i = 0; i < 8; i++) {
            int idx = (i + 2 * s) & 7;                          // bank rotation per slice
            ulonglong2 hv = *(const ulonglong2*)(hb + 4 * idx); // 4 h values as 2x f32x2
            ulonglong2 wv = *(const ulonglong2*)(wop + 4 * i);  // o-gate weights
            a0 = fma2(wr[0 * 16 + 2 * i],     hv.x, a0);
            a0 = fma2(wr[0 * 16 + 2 * i + 1], hv.y, a0);
            a1 = fma2(wr[1 * 16 + 2 * i],     hv.x, a1);
            a1 = fma2(wr[1 * 16 + 2 * i + 1], hv.y, a1);
            a2 = fma2(wr[2 * 16 + 2 * i],     hv.x, a2);
            a2 = fma2(wr[2 * 16 + 2 * i + 1], hv.y, a2);
            a3 = fma2(wv.x, hv.x, a3);
            a3 = fma2(wv.y, hv.y, a3);
        }
        // complete the 128-wide dots across the quad (s = 0..3)
        float v0 = f2sum(a0), v1 = f2sum(a1), v2 = f2sum(a2), v3 = f2sum(a3);
        v0 += __shfl_xor_sync(0xFFFFFFFFu, v0, 1);
        v1 += __shfl_xor_sync(0xFFFFFFFFu, v1, 1);
        v2 += __shfl_xor_sync(0xFFFFFFFFu, v2, 1);
        v3 += __shfl_xor_sync(0xFFFFFFFFu, v3, 1);
        v0 += __shfl_xor_sync(0xFFFFFFFFu, v0, 2);
        v1 += __shfl_xor_sync(0xFFFFFFFFu, v1, 2);
        v2 += __shfl_xor_sync(0xFFFFFFFFu, v2, 2);
        v3 += __shfl_xor_sync(0xFFFFFFFFu, v3, 2);

        // activations (quad-redundant; identical FP sequence -> identical c in all 4 lanes)
        float ig = sigf(v0 + p0);
        float fg = sigf(v1 + p1);
        float gg = tanhfa(v2 + p2);
        float og = sigf(v3 + p3);
        c = fg * c + ig * gg;
        float h = og * tanhfa(c);

        if (s == 0) {
            hbuf[((t + 1) & 1) * HID + j] = h;
            h_out[(t * BB + trace) * HID + j] = h;
        }
        __syncthreads();
    }
}

// ---------------- final linear + gather (unchanged) ----------------
__global__ void __launch_bounds__(256)
final_gather(const float* __restrict__ W_lin,
             const float* __restrict__ b_lin,
             float* __restrict__ y)
{
    int warp = (blockIdx.x * blockDim.x + threadIdx.x) >> 5;
    int lane = threadIdx.x & 31;
    if (warp >= BB * TT) return;
    int trace = warp >> 5;
    int k     = warp & 31;
    const float* hrow = g_h2 + (k * BB + trace) * HID;

    float sv = 0.0f;
#pragma unroll
    for (int h = 0; h < HID; h += 32) sv += hrow[h + lane] * W_lin[h + lane];
#pragma unroll
    for (int o = 16; o > 0; o >>= 1) sv += __shfl_xor_sync(0xFFFFFFFFu, sv, o);
    if (lane == 0) y[warp] = sv + b_lin[0];
}

// ---------------- launch ----------------
extern "C" void kernel_launch(void* const* d_in, const int* in_sizes, int n_in,
                              void* d_out, int out_size)
{
    const float* input = (const float*)d_in[0];
    const float* W_ih0 = (const float*)d_in[1];
    const float* W_hh0 = (const float*)d_in[2];
    const float* b_ih0 = (const float*)d_in[3];
    const float* b_hh0 = (const float*)d_in[4];
    const float* W_ih1 = (const float*)d_in[5];
    const float* W_hh1 = (const float*)d_in[6];
    const float* b_ih1 = (const float*)d_in[7];
    const float* b_hh1 = (const float*)d_in[8];
    const float* W_lin = (const float*)d_in[9];
    const float* b_lin = (const float*)d_in[10];
    float* y = (float*)d_out;

    const int smem = (256 + G4 * WoSTR) * (int)sizeof(float); // 74,752 B
    cudaFuncSetAttribute(lstm_scan, cudaFuncAttributeMaxDynamicSharedMemorySize, smem);

    xproj_gemm<64, true><<<dim3(64, 8), 256>>>(input, W_ih0, b_ih0, b_hh0);
    lstm_scan<<<BB, 512, smem>>>(W_hh0, 0);
    xproj_gemm<128, false><<<dim3(64, 8), 256>>>(nullptr, W_ih1, b_ih1, b_hh1);
    lstm_scan<<<BB, 512, smem>>>(W_hh1, 1);
    final_gather<<<(BB * TT * 32) / 256, 256>>>(W_lin, b_lin, y);
}